// round 15
// baseline (speedup 1.0000x reference)
#include <cuda_runtime.h>
#include <cuda_bf16.h>

#define NPTS   16384
#define B_BAT  8
#define NPOINT 1024
#define NSAMP  32
#define DIN    64
#define CIN0   67
#define H1DIM  64
#define H2DIM  128
#define H3DIM  256
#define NPAIRS 4096   // 8192 groups / 2, paired as (s, b-even/odd)

// Scratch (device globals; no runtime allocation)
__device__ int      g_fps[B_BAT * NPOINT];
__device__ unsigned g_prog[B_BAT];   // fps progress per batch (release/acquire)
__device__ unsigned g_q;             // mlp work queue counter

// exact (non-contracted) squared distance, XLA reduce order ((dx^2+dy^2)+dz^2)
__device__ __forceinline__ float sqdist(float dx, float dy, float dz) {
    return __fadd_rn(__fadd_rn(__fmul_rn(dx, dx), __fmul_rn(dy, dy)), __fmul_rn(dz, dz));
}

__device__ __forceinline__ float silu_f(float x) {
    return __fdividef(x, 1.0f + __expf(-x));
}

// ---- packed fp32x2 helpers (sm_103a FFMA2 path) ----
#define FMA2(acc, x, w) asm("fma.rn.f32x2 %0, %1, %2, %0;" : "+l"(acc) : "l"(x), "l"(w))
#define PACK2(d, s)     asm("mov.b64 %0, {%1, %1};" : "=l"(d) : "f"(s))
#define PACKAB(d, a, b) asm("mov.b64 %0, {%1, %2};" : "=l"(d) : "f"(a), "f"(b))
#define UNPACK2(lo, hi, v) asm("mov.b64 {%0, %1}, %2;" : "=f"(lo), "=f"(hi) : "l"(v))
#define ADDX2(d, a, b)  asm("add.rn.f32x2 %0, %1, %2;" : "=l"(d) : "l"(a), "l"(b))
#define MULX2(d, a, b)  asm("mul.rn.f32x2 %0, %1, %2;" : "=l"(d) : "l"(a), "l"(b))

#define ST_REL(addr, val) \
    asm volatile("st.release.gpu.u32 [%0], %1;" :: "l"(addr), "r"(val) : "memory")
#define LD_ACQ(val, addr) \
    asm volatile("ld.acquire.gpu.u32 %0, [%1];" : "=r"(val) : "l"(addr) : "memory")

// XOR-4 swizzle on the k index, keyed by row c; period 32 in c so cb-blocked
// unrolled loops fold it to compile-time immediates.
#define SWZ(c, k) ((k) ^ ((((c) >> 2) & 7) << 2))

// ---------------------------------------------------------------------------
// Kernel 1: farthest point sampling, 8-CTA cluster per batch (R14 form) +
// per-step progress publication: warp1 lane0 of rank0 writes g_fps[b][s]
// then st.release g_prog[b] = s+1 (off the warp0 publish critical path).
// ---------------------------------------------------------------------------
__global__ void __launch_bounds__(256, 1) __cluster_dims__(8, 1, 1)
fps_kernel(const float* __restrict__ xyz) {
    extern __shared__ float sm[];
    float* sx = sm;              // [16384]
    float* sy = sm + NPTS;       // [16384]
    float* sz = sm + 2 * NPTS;   // [16384]
    __shared__ unsigned long long slots[2][8];   // [buf][src_rank]
    __shared__ unsigned long long s_key[8];

    unsigned rank;
    asm("mov.u32 %0, %%cluster_ctarank;" : "=r"(rank));
    const int b = blockIdx.x >> 3;
    const int t = threadIdx.x;
    const int lane = t & 31;
    const int w = t >> 5;
    const float* px = xyz + (size_t)b * 3 * NPTS;
    const int base = (int)rank * 2048;

    unsigned slot_base;
    asm("{ .reg .u64 tt; cvta.to.shared.u64 tt, %1; cvt.u32.u64 %0, tt; }"
        : "=r"(slot_base) : "l"(&slots[0][0]));

    // stage the full cloud (coalesced)
    for (int i = t; i < NPTS; i += 256) {
        sx[i] = px[i];
        sy[i] = px[NPTS + i];
        sz[i] = px[2 * NPTS + i];
    }
    __syncthreads();

    // own 2048-point range, packed in pairs (p, p+256)
    unsigned long long xp[4], yp[4], zp[4];
    float dist[8];
#pragma unroll
    for (int j2 = 0; j2 < 4; j2++) {
        int p0 = base + (2 * j2) * 256 + t;
        int p1 = p0 + 256;
        PACKAB(xp[j2], sx[p0], sx[p1]);
        PACKAB(yp[j2], sy[p0], sy[p1]);
        PACKAB(zp[j2], sz[p0], sz[p1]);
        dist[2 * j2]     = __int_as_float(0x7f800000);
        dist[2 * j2 + 1] = __int_as_float(0x7f800000);
    }
    float cx = sx[0], cy = sy[0], cz = sz[0];
    int cur = 0;

    for (int s = 0; s < NPOINT; s++) {
        if (rank == 0 && t == 32) {               // warp1 lane0: publish progress
            g_fps[b * NPOINT + s] = cur;
            ST_REL(&g_prog[b], (unsigned)(s + 1));
        }

        // packed negated centroid (negation exact; x + (-c) == x - c bitwise)
        unsigned long long ncx2, ncy2, ncz2;
        PACK2(ncx2, -cx); PACK2(ncy2, -cy); PACK2(ncz2, -cz);

        float bv = -1.0f;
        int   bi = 0;
#pragma unroll
        for (int j2 = 0; j2 < 4; j2++) {
            unsigned long long dx, dy, dz, ss;
            ADDX2(dx, xp[j2], ncx2);
            ADDX2(dy, yp[j2], ncy2);
            ADDX2(dz, zp[j2], ncz2);
            MULX2(dx, dx, dx);
            MULX2(dy, dy, dy);
            MULX2(dz, dz, dz);
            ADDX2(ss, dx, dy);
            ADDX2(ss, ss, dz);
            float d0, d1;
            UNPACK2(d0, d1, ss);
            float nd0 = fminf(dist[2 * j2], d0);
            float nd1 = fminf(dist[2 * j2 + 1], d1);
            dist[2 * j2] = nd0;
            dist[2 * j2 + 1] = nd1;
            int p0 = base + (2 * j2) * 256 + t;
            if (nd0 > bv) { bv = nd0; bi = p0; }          // ascending index order
            if (nd1 > bv) { bv = nd1; bi = p0 + 256; }    // => first occurrence
        }
        // warp argmax (val desc, idx asc on tie)
        unsigned vb = __float_as_uint(bv);
        unsigned mv = __reduce_max_sync(0xffffffffu, vb);
        unsigned ic = (vb == mv) ? (unsigned)bi : 0xffffffffu;
        unsigned mi = __reduce_min_sync(0xffffffffu, ic);
        if (lane == 0)
            s_key[w] = ((unsigned long long)mv << 32)
                     | (unsigned long long)(16383u - mi);
        __syncthreads();

        // warp 0: reduce the 8 warp keys, lanes 0-7 publish to the 8 ranks
        if (w == 0) {
            unsigned long long k = s_key[lane & 7];
#pragma unroll
            for (int off = 4; off; off >>= 1) {
                unsigned long long ok = __shfl_xor_sync(0xffffffffu, k, off);
                if (ok > k) k = ok;
            }
            if (lane < 8) {
                unsigned la = slot_base + (unsigned)(((s & 1) * 8 + (int)rank) * 8);
                unsigned ra;
                asm("mapa.shared::cluster.u32 %0, %1, %2;" : "=r"(ra) : "r"(la), "r"(lane));
                asm volatile("st.shared::cluster.b64 [%0], %1;" :: "r"(ra), "l"(k));
            }
        }
        asm volatile("barrier.cluster.arrive.aligned;" ::: "memory");
        asm volatile("barrier.cluster.wait.aligned;"   ::: "memory");

        // resolve global winner (identical in every CTA)
        const unsigned long long* rec = &slots[s & 1][0];
        unsigned long long gk = rec[0];
#pragma unroll
        for (int r = 1; r < 8; r++) {
            unsigned long long fk = rec[r];
            if (fk > gk) gk = fk;
        }
        cur = 16383 - (int)(gk & 0x3fffu);
        cx = sx[cur]; cy = sy[cur]; cz = sz[cur];
    }
}

// ---------------------------------------------------------------------------
// Kernel 2: work-queue MLP. CTAs pop pairs p from g_q: s = p>>2,
// batches (2*(p&3), 2*(p&3)+1). Gate on g_prog (acquire), then inline
// ball-query (warps 0/1), gather, 3 FFMA2 layers, mean, out.
// Launched twice: 64 CTAs concurrent with fps (side stream), 84 after fps.
// ---------------------------------------------------------------------------
#define SM_W0   0
#define SM_W1   4288
#define SM_W2   12480
#define SM_X0   45248
#define SM_H2   45248
#define SM_H1   53440
#define SM_RED  53440
#define SM_NBR  57536
#define SM_Q    57600
#define MLP_SMEM_FLOATS 57608

__global__ void __launch_bounds__(512, 1)
mlp_kernel(const float* __restrict__ xyz, const float* __restrict__ pts,
           const float* __restrict__ w0, const float* __restrict__ w1,
           const float* __restrict__ w2,
           const float* __restrict__ b0, const float* __restrict__ b1,
           const float* __restrict__ b2, float* __restrict__ out) {
    extern __shared__ float smf[];
    float* W0t = smf + SM_W0;
    float* W1t = smf + SM_W1;
    float* W2t = smf + SM_W2;
    float* X0t = smf + SM_X0;   // [67][64]
    float* H2t = smf + SM_H2;   // [128][64], k swizzled
    float* H1t = smf + SM_H1;   // [64][64], k swizzled
    float* Red = smf + SM_RED;  // [8][256]
    int*   nbr = (int*)(smf + SM_NBR);
    float* qp  = smf + SM_Q;
    __shared__ unsigned sm_pair;

    const int t = threadIdx.x;
    const int w = t >> 5;
    const int lane = t & 31;

    // stage weights: direct transpose from gmem (L2-hot, once per CTA)
    for (int i = t; i < 4288; i += 512)  { int c = i >> 6, o = i & 63;  W0t[i] = w0[o * CIN0 + c]; }
    for (int i = t; i < 8192; i += 512)  { int c = i >> 7, o = i & 127; W1t[i] = w1[o * H1DIM + c]; }
    for (int i = t; i < 32768; i += 512) { int c = i >> 8, o = i & 255; W2t[i] = w2[o * H2DIM + c]; }

    const int o0 = (t & 15) * 4, k0a = (t >> 4) * 2;   // L0: 2k x 4o
    const int o1 = (t & 31) * 4, k1  = (t >> 5) * 4;   // L1: 4k x 4o
    const int o2 = (t & 63) * 4, kt2 = (t >> 6);       // L2: 8k x 4o
    const int k2 = kt2 * 8;

    float bias0[4], bias1[4], bias2[4];
#pragma unroll
    for (int i = 0; i < 4; i++) bias0[i] = b0[o0 + i];
#pragma unroll
    for (int i = 0; i < 4; i++) bias1[i] = b1[o1 + i];
#pragma unroll
    for (int i = 0; i < 4; i++) bias2[i] = b2[o2 + i];
    __syncthreads();

    while (true) {
        // pop + gate (t0), broadcast via smem
        if (t == 0) {
            unsigned p = atomicAdd(&g_q, 1u);
            if (p < NPAIRS) {
                int s = (int)(p >> 2);
                int bb = ((int)p & 3) * 2;
                unsigned v;
                do { LD_ACQ(v, &g_prog[bb]); }     while (v <= (unsigned)s);
                do { LD_ACQ(v, &g_prog[bb + 1]); } while (v <= (unsigned)s);
            }
            sm_pair = p;
        }
        __syncthreads();
        const unsigned pr = sm_pair;
        if (pr >= NPAIRS) break;
        const int s   = (int)(pr >> 2);
        const int bb0 = ((int)pr & 3) * 2;

        // inline ball query: warp gi in {0,1} handles group gi
        if (w < 2) {
            const int b = bb0 + w;
            const float* px = xyz + (size_t)b * 3 * NPTS;
            const int qi = g_fps[b * NPOINT + s];
            const float qx = px[qi], qy = px[NPTS + qi], qz = px[2 * NPTS + qi];
            if (lane == 0) { qp[w * 3 + 0] = qx; qp[w * 3 + 1] = qy; qp[w * 3 + 2] = qz; }
            int cnt = 0;
            int first = 0;
            for (int ch = 0; ch < NPTS / 32; ch++) {
                if (cnt >= NSAMP) break;
                int pt = ch * 32 + lane;
                float dx = __fsub_rn(px[pt], qx);
                float dy = __fsub_rn(px[NPTS + pt], qy);
                float dz = __fsub_rn(px[2 * NPTS + pt], qz);
                float d  = sqdist(dx, dy, dz);
                bool ok = !(d > 0.04f);
                unsigned mask = __ballot_sync(0xffffffffu, ok);
                if (cnt == 0 && mask) first = ch * 32 + (__ffs(mask) - 1);
                int rnk = cnt + __popc(mask & ((1u << lane) - 1u));
                if (ok && rnk < NSAMP) nbr[w * 32 + rnk] = pt;
                cnt += __popc(mask);
            }
            if (cnt < NSAMP) {
                for (int r = cnt + lane; r < NSAMP; r += 32)
                    nbr[w * 32 + r] = first;
            }
        }
        __syncthreads();

        // gather X0t[c][k]
        {
            const float* px0 = xyz + (size_t)bb0 * 3 * NPTS;
            const float* pp0 = pts + (size_t)bb0 * DIN * NPTS;
            const float* px1 = px0 + 3 * NPTS;
            const float* pp1 = pp0 + DIN * NPTS;
            for (int j = t; j < 64 * CIN0; j += 512) {
                int c = j >> 6, k = j & 63;
                int gi = k >> 5;
                int nk = nbr[k];
                const float* px = gi ? px1 : px0;
                const float* pp = gi ? pp1 : pp0;
                float v = (c < 3) ? (px[c * NPTS + nk] - qp[gi * 3 + c])
                                  : pp[(c - 3) * NPTS + nk];
                X0t[c * 64 + k] = v;
            }
        }
        __syncthreads();

        // ---- Layer 0: 67 -> 64, tile 2k x 4o ----
        {
            unsigned long long a00 = 0, a01 = 0, a10 = 0, a11 = 0;
#pragma unroll 4
            for (int c = 0; c < CIN0; c++) {
                float2 xv = *(const float2*)&X0t[c * 64 + k0a];
                ulonglong2 wv = *(const ulonglong2*)&W0t[c * 64 + o0];
                unsigned long long x0, x1;
                PACK2(x0, xv.x); PACK2(x1, xv.y);
                FMA2(a00, x0, wv.x); FMA2(a01, x0, wv.y);
                FMA2(a10, x1, wv.x); FMA2(a11, x1, wv.y);
            }
            float v[2][4];
            UNPACK2(v[0][0], v[0][1], a00); UNPACK2(v[0][2], v[0][3], a01);
            UNPACK2(v[1][0], v[1][1], a10); UNPACK2(v[1][2], v[1][3], a11);
#pragma unroll
            for (int j = 0; j < 4; j++) {
                int c = o0 + j;
                float2 hv = make_float2(silu_f(v[0][j] + bias0[j]),
                                        silu_f(v[1][j] + bias0[j]));
                *(float2*)&H1t[c * 64 + SWZ(c, k0a)] = hv;
            }
        }
        __syncthreads();

        // ---- Layer 1: 64 -> 128, tile 4k x 4o; cb-blocked const swizzle ----
        {
            unsigned long long a[2][4];
#pragma unroll
            for (int kp = 0; kp < 2; kp++)
#pragma unroll
                for (int j = 0; j < 4; j++) a[kp][j] = 0;
            const float* h1b = H1t + k1;
            const float* w1b = W1t + o1;
            for (int cb = 0; cb < H1DIM; cb += 32) {
#pragma unroll
                for (int u = 0; u < 32; u++) {
                    const int c = cb + u;
                    ulonglong2 xv = *(const ulonglong2*)&h1b[c * 64 + (SWZ(c, k1) - k1)];
                    float4 wv = *(const float4*)&w1b[c * 128];
                    unsigned long long w0d, w1d, w2d, w3d;
                    PACK2(w0d, wv.x); PACK2(w1d, wv.y); PACK2(w2d, wv.z); PACK2(w3d, wv.w);
                    FMA2(a[0][0], xv.x, w0d); FMA2(a[0][1], xv.x, w1d);
                    FMA2(a[0][2], xv.x, w2d); FMA2(a[0][3], xv.x, w3d);
                    FMA2(a[1][0], xv.y, w0d); FMA2(a[1][1], xv.y, w1d);
                    FMA2(a[1][2], xv.y, w2d); FMA2(a[1][3], xv.y, w3d);
                }
            }
            float v[4][4];
#pragma unroll
            for (int kp = 0; kp < 2; kp++)
#pragma unroll
                for (int j = 0; j < 4; j++)
                    UNPACK2(v[2 * kp][j], v[2 * kp + 1][j], a[kp][j]);
#pragma unroll
            for (int j = 0; j < 4; j++) {
                int c = o1 + j;
                float4 hv = make_float4(silu_f(v[0][j] + bias1[j]),
                                        silu_f(v[1][j] + bias1[j]),
                                        silu_f(v[2][j] + bias1[j]),
                                        silu_f(v[3][j] + bias1[j]));
                *(float4*)&H2t[c * 64 + SWZ(c, k1)] = hv;
            }
        }
        __syncthreads();

        // ---- Layer 2: 128 -> 256, tile 8k x 4o; cb-blocked const swizzle ----
        {
            unsigned long long a[4][4];
#pragma unroll
            for (int kp = 0; kp < 4; kp++)
#pragma unroll
                for (int j = 0; j < 4; j++) a[kp][j] = 0;
            const float* h2a = H2t + k2;
            const float* h2b = H2t + k2 + 4;
            const float* w2b = W2t + o2;
            for (int cb = 0; cb < H2DIM; cb += 32) {
#pragma unroll
                for (int u = 0; u < 32; u++) {
                    const int c = cb + u;
                    ulonglong2 xa = *(const ulonglong2*)&h2a[c * 64 + (SWZ(c, k2) - k2)];
                    ulonglong2 xb = *(const ulonglong2*)&h2b[c * 64 + (SWZ(c, k2 + 4) - (k2 + 4))];
                    float4 wv = *(const float4*)&w2b[c * 256];
                    unsigned long long w0d, w1d, w2d, w3d;
                    PACK2(w0d, wv.x); PACK2(w1d, wv.y); PACK2(w2d, wv.z); PACK2(w3d, wv.w);
                    FMA2(a[0][0], xa.x, w0d); FMA2(a[0][1], xa.x, w1d);
                    FMA2(a[0][2], xa.x, w2d); FMA2(a[0][3], xa.x, w3d);
                    FMA2(a[1][0], xa.y, w0d); FMA2(a[1][1], xa.y, w1d);
                    FMA2(a[1][2], xa.y, w2d); FMA2(a[1][3], xa.y, w3d);
                    FMA2(a[2][0], xb.x, w0d); FMA2(a[2][1], xb.x, w1d);
                    FMA2(a[2][2], xb.x, w2d); FMA2(a[2][3], xb.x, w3d);
                    FMA2(a[3][0], xb.y, w0d); FMA2(a[3][1], xb.y, w1d);
                    FMA2(a[3][2], xb.y, w2d); FMA2(a[3][3], xb.y, w3d);
                }
            }
            float u2[8][4];
#pragma unroll
            for (int kp = 0; kp < 4; kp++)
#pragma unroll
                for (int j = 0; j < 4; j++)
                    UNPACK2(u2[2 * kp][j], u2[2 * kp + 1][j], a[kp][j]);
            float part[4];
#pragma unroll
            for (int j = 0; j < 4; j++) {
                float bb = bias2[j];
                float sum = silu_f(u2[0][j] + bb);
#pragma unroll
                for (int kk = 1; kk < 8; kk++) sum += silu_f(u2[kk][j] + bb);
                part[j] = sum;
            }
            // Red aliases H1t: last H1t reads completed at the post-L1 sync
            *(float4*)&Red[kt2 * 256 + o2] = make_float4(part[0], part[1], part[2], part[3]);
        }
        __syncthreads();

        // mean over 32 samples; gi = t>>8 selects group, o = t&255
        {
            int gi = t >> 8;
            int o  = t & 255;
            float sum = 0.0f;
#pragma unroll
            for (int r = 0; r < 4; r++) sum += Red[(gi * 4 + r) * 256 + o];
            int b = bb0 + gi;
            out[(size_t)b * (H3DIM * NPOINT) + (size_t)o * NPOINT + s] = sum * (1.0f / 32.0f);
        }
        __syncthreads();
    }
}

// ---------------------------------------------------------------------------
// Kernel 3: reset queue/progress for the next graph replay.
// ---------------------------------------------------------------------------
__global__ void reset_kernel() {
    if (threadIdx.x < B_BAT) g_prog[threadIdx.x] = 0;
    if (threadIdx.x == 0) g_q = 0;
}

// ---------------------------------------------------------------------------
extern "C" void kernel_launch(void* const* d_in, const int* in_sizes, int n_in,
                              void* d_out, int out_size) {
    const float* xyz = (const float*)d_in[0];
    const float* pts = (const float*)d_in[1];
    const float* w0  = (const float*)d_in[2];
    const float* b0  = (const float*)d_in[3];
    const float* w1  = (const float*)d_in[4];
    const float* b1  = (const float*)d_in[5];
    const float* w2  = (const float*)d_in[6];
    const float* b2  = (const float*)d_in[7];
    float* out = (float*)d_out;

    const int fps_smem = 3 * NPTS * (int)sizeof(float);           // 196608 B
    const int mlp_smem = MLP_SMEM_FLOATS * (int)sizeof(float);    // 230432 B
    cudaFuncSetAttribute(fps_kernel, cudaFuncAttributeMaxDynamicSharedMemorySize, fps_smem);
    cudaFuncSetAttribute(mlp_kernel, cudaFuncAttributeMaxDynamicSharedMemorySize, mlp_smem);

    // fork: mlp-A (64 CTAs) runs concurrently with fps; mlp-B (84) after fps.
    cudaStream_t sA;
    cudaStreamCreateWithFlags(&sA, cudaStreamNonBlocking);
    cudaEvent_t e1, e2;
    cudaEventCreateWithFlags(&e1, cudaEventDisableTiming);
    cudaEventCreateWithFlags(&e2, cudaEventDisableTiming);

    cudaEventRecord(e1, 0);
    cudaStreamWaitEvent(sA, e1, 0);
    mlp_kernel<<<64, 512, mlp_smem, sA>>>(xyz, pts, w0, w1, w2, b0, b1, b2, out);
    cudaEventRecord(e2, sA);

    fps_kernel<<<B_BAT * 8, 256, fps_smem>>>(xyz);
    mlp_kernel<<<84, 512, mlp_smem>>>(xyz, pts, w0, w1, w2, b0, b1, b2, out);

    cudaStreamWaitEvent(0, e2, 0);
    reset_kernel<<<1, 32>>>();
}

// round 16
// speedup vs baseline: 1.8403x; 1.8403x over previous
#include <cuda_runtime.h>
#include <cuda_bf16.h>

#define NPTS   16384
#define B_BAT  8
#define NPOINT 1024
#define NSAMP  32
#define DIN    64
#define CIN0   67
#define H1DIM  64
#define H2DIM  128
#define H3DIM  256

// Scratch (device globals; no runtime allocation)
__device__ int   g_fps[B_BAT * NPOINT];
__device__ int   g_nb[B_BAT * NPOINT * NSAMP];
__device__ float g_Wt[4288 + 8192 + 32768];   // W0t(67x64) | W1t(64x128) | W2t(128x256)

// exact (non-contracted) squared distance, XLA reduce order ((dx^2+dy^2)+dz^2)
__device__ __forceinline__ float sqdist(float dx, float dy, float dz) {
    return __fadd_rn(__fadd_rn(__fmul_rn(dx, dx), __fmul_rn(dy, dy)), __fmul_rn(dz, dz));
}

__device__ __forceinline__ float silu_f(float x) {
    return __fdividef(x, 1.0f + __expf(-x));
}

// ---- packed fp32x2 helpers (sm_103a FFMA2 path) ----
#define FMA2(acc, x, w) asm("fma.rn.f32x2 %0, %1, %2, %0;" : "+l"(acc) : "l"(x), "l"(w))
#define PACK2(d, s)     asm("mov.b64 %0, {%1, %1};" : "=l"(d) : "f"(s))
#define PACKAB(d, a, b) asm("mov.b64 %0, {%1, %2};" : "=l"(d) : "f"(a), "f"(b))
#define UNPACK2(lo, hi, v) asm("mov.b64 {%0, %1}, %2;" : "=f"(lo), "=f"(hi) : "l"(v))
#define ADDX2(d, a, b)  asm("add.rn.f32x2 %0, %1, %2;" : "=l"(d) : "l"(a), "l"(b))
#define MULX2(d, a, b)  asm("mul.rn.f32x2 %0, %1, %2;" : "=l"(d) : "l"(a), "l"(b))

// XOR-4 swizzle on the k index, keyed by row c; period 32 in c so cb-blocked
// unrolled loops fold it to compile-time immediates.
#define SWZ(c, k) ((k) ^ ((((c) >> 2) & 7) << 2))

// Tagged key layout: [dist:32 | zero:16 | tag:2 | inv_idx:14]
// tag = step & 3 identical across CTAs at a step, so u64-max ordering is
// (dist desc, idx asc). inv_idx = 16383 - idx.
#define KEY_TAG(k)  ((unsigned)(((k) >> 14) & 3ull))
#define KEY_IDX(k)  (16383 - (int)((k) & 0x3fffull))

// ---------------------------------------------------------------------------
// Kernel 1: farthest point sampling, 8-CTA cluster per batch.
// Cross-CTA sync WITHOUT barrier.cluster: each step, warp0 lanes 0-7 push a
// single tagged u64 key to all ranks via st.relaxed.cluster (8B single-copy
// atomic: data+tag arrive together); everyone spins on local LDS until all
// 8 slots carry tag (s&3). Double-buffered by s&1; a rank writes step s+2
// only after passing its s+1 wait => all ranks finished reading step s, and
// stale/fresh tags in a buffer differ by 2 mod 4 (never confusable).
// ---------------------------------------------------------------------------
__global__ void __launch_bounds__(256, 1) __cluster_dims__(8, 1, 1)
fps_kernel(const float* __restrict__ xyz) {
    extern __shared__ float sm[];
    float* sx = sm;              // [16384]
    float* sy = sm + NPTS;       // [16384]
    float* sz = sm + 2 * NPTS;   // [16384]
    __shared__ unsigned long long slots[2][8];   // [buf][src_rank], tagged keys
    __shared__ unsigned long long s_key[8];

    unsigned rank;
    asm("mov.u32 %0, %%cluster_ctarank;" : "=r"(rank));
    const int b = blockIdx.x >> 3;
    const int t = threadIdx.x;
    const int lane = t & 31;
    const int w = t >> 5;
    const float* px = xyz + (size_t)b * 3 * NPTS;
    const int base = (int)rank * 2048;

    unsigned slot_base;
    asm("{ .reg .u64 tt; cvta.to.shared.u64 tt, %1; cvt.u32.u64 %0, tt; }"
        : "=r"(slot_base) : "l"(&slots[0][0]));

    // init all slots with impossible tag 3... (first uses want tags 0 and 1;
    // later reuses always differ by 2 mod 4 from the stale tag)
    if (t < 16) slots[t >> 3][t & 7] = (3ull << 14);
    __syncthreads();
    // slots must be initialized cluster-wide before any remote store lands
    asm volatile("barrier.cluster.arrive.aligned;" ::: "memory");
    asm volatile("barrier.cluster.wait.aligned;"   ::: "memory");

    // stage the full cloud (coalesced)
    for (int i = t; i < NPTS; i += 256) {
        sx[i] = px[i];
        sy[i] = px[NPTS + i];
        sz[i] = px[2 * NPTS + i];
    }
    __syncthreads();

    // own 2048-point range, packed in pairs (p, p+256)
    unsigned long long xp[4], yp[4], zp[4];
    float dist[8];
#pragma unroll
    for (int j2 = 0; j2 < 4; j2++) {
        int p0 = base + (2 * j2) * 256 + t;
        int p1 = p0 + 256;
        PACKAB(xp[j2], sx[p0], sx[p1]);
        PACKAB(yp[j2], sy[p0], sy[p1]);
        PACKAB(zp[j2], sz[p0], sz[p1]);
        dist[2 * j2]     = __int_as_float(0x7f800000);
        dist[2 * j2 + 1] = __int_as_float(0x7f800000);
    }
    float cx = sx[0], cy = sy[0], cz = sz[0];
    int cur = 0;

    for (int s = 0; s < NPOINT; s++) {
        if (rank == 0 && t == 32) g_fps[b * NPOINT + s] = cur;  // warp1 lane0

        // packed negated centroid (negation exact; x + (-c) == x - c bitwise)
        unsigned long long ncx2, ncy2, ncz2;
        PACK2(ncx2, -cx); PACK2(ncy2, -cy); PACK2(ncz2, -cz);

        float bv = -1.0f;
        int   bi = 0;
#pragma unroll
        for (int j2 = 0; j2 < 4; j2++) {
            unsigned long long dx, dy, dz, ss;
            ADDX2(dx, xp[j2], ncx2);
            ADDX2(dy, yp[j2], ncy2);
            ADDX2(dz, zp[j2], ncz2);
            MULX2(dx, dx, dx);
            MULX2(dy, dy, dy);
            MULX2(dz, dz, dz);
            ADDX2(ss, dx, dy);
            ADDX2(ss, ss, dz);
            float d0, d1;
            UNPACK2(d0, d1, ss);
            float nd0 = fminf(dist[2 * j2], d0);
            float nd1 = fminf(dist[2 * j2 + 1], d1);
            dist[2 * j2] = nd0;
            dist[2 * j2 + 1] = nd1;
            int p0 = base + (2 * j2) * 256 + t;
            if (nd0 > bv) { bv = nd0; bi = p0; }          // ascending index order
            if (nd1 > bv) { bv = nd1; bi = p0 + 256; }    // => first occurrence
        }
        // warp argmax (val desc, idx asc on tie)
        unsigned vb = __float_as_uint(bv);
        unsigned mv = __reduce_max_sync(0xffffffffu, vb);
        unsigned ic = (vb == mv) ? (unsigned)bi : 0xffffffffu;
        unsigned mi = __reduce_min_sync(0xffffffffu, ic);
        if (lane == 0)
            s_key[w] = ((unsigned long long)mv << 32)
                     | (unsigned long long)(16383u - mi);
        __syncthreads();

        // warp 0: reduce the 8 warp keys; lanes 0-7 push tagged key to ranks
        if (w == 0) {
            unsigned long long k = s_key[lane & 7];
#pragma unroll
            for (int off = 4; off; off >>= 1) {
                unsigned long long ok = __shfl_xor_sync(0xffffffffu, k, off);
                if (ok > k) k = ok;
            }
            if (lane < 8) {
                unsigned long long kt = k | ((unsigned long long)(s & 3) << 14);
                unsigned la = slot_base + (unsigned)(((s & 1) * 8 + (int)rank) * 8);
                unsigned ra;
                asm("mapa.shared::cluster.u32 %0, %1, %2;" : "=r"(ra) : "r"(la), "r"(lane));
                asm volatile("st.relaxed.cluster.shared::cluster.b64 [%0], %1;"
                             :: "r"(ra), "l"(kt) : "memory");
            }
        }

        // spin until all 8 slots of this buffer carry tag s&3 (local LDS poll;
        // 8B relaxed loads are single-copy atomic, tag travels with data)
        unsigned long long kk[8];
        {
            const unsigned want = (unsigned)(s & 3);
            unsigned lb = slot_base + (unsigned)((s & 1) * 8) * 8u;
            bool ok;
            do {
                ok = true;
#pragma unroll
                for (int r = 0; r < 8; r++) {
                    asm volatile("ld.relaxed.cluster.shared::cta.b64 %0, [%1];"
                                 : "=l"(kk[r]) : "r"(lb + (unsigned)(r * 8)) : "memory");
                    ok &= (KEY_TAG(kk[r]) == want);
                }
            } while (!ok);
        }

        // resolve global winner (identical in every CTA): u64 max, tree
        unsigned long long m01 = kk[0] > kk[1] ? kk[0] : kk[1];
        unsigned long long m23 = kk[2] > kk[3] ? kk[2] : kk[3];
        unsigned long long m45 = kk[4] > kk[5] ? kk[4] : kk[5];
        unsigned long long m67 = kk[6] > kk[7] ? kk[6] : kk[7];
        unsigned long long m03 = m01 > m23 ? m01 : m23;
        unsigned long long m47 = m45 > m67 ? m45 : m67;
        unsigned long long gk  = m03 > m47 ? m03 : m47;
        cur = KEY_IDX(gk);
        cx = sx[cur]; cy = sy[cur]; cz = sz[cur];
    }
}

// ---------------------------------------------------------------------------
// Kernel 2: ball query (blocks < 1024) + weight transpose (blocks >= 1024).
// ---------------------------------------------------------------------------
#define BQ_BLOCKS   1024
#define PREP_BLOCKS 177   // ceil(45248 / 256)

__global__ void bq_prep_kernel(const float* __restrict__ xyz,
                               const float* __restrict__ w0,
                               const float* __restrict__ w1,
                               const float* __restrict__ w2) {
    if (blockIdx.x >= BQ_BLOCKS) {
        // ---- prep: transpose weights into g_Wt as Wt[c][o] ----
        int i = (blockIdx.x - BQ_BLOCKS) * 256 + threadIdx.x;
        if (i < 4288) {
            int c = i >> 6, o = i & 63;
            g_Wt[i] = w0[o * CIN0 + c];
        } else if (i < 4288 + 8192) {
            int j = i - 4288;
            int c = j >> 7, o = j & 127;
            g_Wt[i] = w1[o * H1DIM + c];
        } else if (i < 4288 + 8192 + 32768) {
            int j = i - (4288 + 8192);
            int c = j >> 8, o = j & 255;
            g_Wt[i] = w2[o * H2DIM + c];
        }
        return;
    }

    // ---- ball query: one warp per (b,s); ordered ballot scan, early exit ----
    const int warp = (blockIdx.x * blockDim.x + threadIdx.x) >> 5;
    const int lane = threadIdx.x & 31;
    const int b = warp >> 10;

    const float* px = xyz + (size_t)b * 3 * NPTS;
    const int qi = g_fps[warp];
    const float qx = px[qi], qy = px[NPTS + qi], qz = px[2 * NPTS + qi];

    int cnt = 0;
    int first = 0;
    for (int ch = 0; ch < NPTS / 32; ch++) {
        if (cnt >= NSAMP) break;
        int p = ch * 32 + lane;
        float dx = __fsub_rn(px[p], qx);
        float dy = __fsub_rn(px[NPTS + p], qy);
        float dz = __fsub_rn(px[2 * NPTS + p], qz);
        float d  = sqdist(dx, dy, dz);
        bool ok = !(d > 0.04f);
        unsigned mask = __ballot_sync(0xffffffffu, ok);
        if (cnt == 0 && mask) first = ch * 32 + (__ffs(mask) - 1);
        int rank = cnt + __popc(mask & ((1u << lane) - 1u));
        if (ok && rank < NSAMP) g_nb[warp * NSAMP + rank] = p;
        cnt += __popc(mask);
    }
    if (cnt < NSAMP) {
        for (int r = cnt + lane; r < NSAMP; r += 32)
            g_nb[warp * NSAMP + r] = first;
    }
}

// ---------------------------------------------------------------------------
// Kernel 3: fused gather + MLP + mean (R13/R14 winner, unchanged).
// ---------------------------------------------------------------------------
#define SM_W0   0
#define SM_W1   4288
#define SM_W2   12480
#define SM_X0   45248
#define SM_H2   45248
#define SM_H1   53440
#define SM_RED  53440
#define SM_NBR  57536
#define SM_Q    57600
#define MLP_SMEM_FLOATS 57608

__global__ void __launch_bounds__(512, 1)
mlp_kernel(const float* __restrict__ xyz, const float* __restrict__ pts,
           const float* __restrict__ b0, const float* __restrict__ b1,
           const float* __restrict__ b2, float* __restrict__ out) {
    extern __shared__ float smf[];
    float* W0t = smf + SM_W0;
    float* W1t = smf + SM_W1;
    float* W2t = smf + SM_W2;
    float* X0t = smf + SM_X0;   // [67][64]
    float* H2t = smf + SM_H2;   // [128][64], k swizzled
    float* H1t = smf + SM_H1;   // [64][64], k swizzled
    float* Red = smf + SM_RED;  // [8][256]
    int*   nbr = (int*)(smf + SM_NBR);
    float* qp  = smf + SM_Q;

    const int t = threadIdx.x;
    const int NG = (B_BAT * NPOINT) / 2;

    {
        const float4* src = (const float4*)g_Wt;
        float4* dst = (float4*)smf;
        for (int i = t; i < 45248 / 4; i += 512) dst[i] = src[i];
    }

    const int o0 = (t & 15) * 4, k0a = (t >> 4) * 2;   // L0: 2k x 4o
    const int o1 = (t & 31) * 4, k1  = (t >> 5) * 4;   // L1: 4k x 4o
    const int o2 = (t & 63) * 4, kt2 = (t >> 6);       // L2: 8k x 4o
    const int k2 = kt2 * 8;

    float bias0[4], bias1[4], bias2[4];
#pragma unroll
    for (int i = 0; i < 4; i++) bias0[i] = b0[o0 + i];
#pragma unroll
    for (int i = 0; i < 4; i++) bias1[i] = b1[o1 + i];
#pragma unroll
    for (int i = 0; i < 4; i++) bias2[i] = b2[o2 + i];

    // stage first group's nbr/qp (covered by the same sync as the weights)
    if (blockIdx.x < NG) {
        const int g0 = blockIdx.x * 2;
        if (t < 64) nbr[t] = g_nb[(g0 + (t >> 5)) * NSAMP + (t & 31)];
        if (t >= 64 && t < 66) {
            int gi = t - 64;
            int g = g0 + gi;
            int b = g >> 10;
            const float* px = xyz + (size_t)b * 3 * NPTS;
            int qi = g_fps[g];
            qp[gi * 3 + 0] = px[qi];
            qp[gi * 3 + 1] = px[NPTS + qi];
            qp[gi * 3 + 2] = px[2 * NPTS + qi];
        }
    }
    __syncthreads();

    for (int pg = blockIdx.x; pg < NG; pg += gridDim.x) {
        const int g0 = pg * 2;

        // gather X0t[c][k]
        {
            const int b0i = g0 >> 10;
            const int b1i = (g0 + 1) >> 10;
            const float* px0 = xyz + (size_t)b0i * 3 * NPTS;
            const float* pp0 = pts + (size_t)b0i * DIN * NPTS;
            const float* px1 = xyz + (size_t)b1i * 3 * NPTS;
            const float* pp1 = pts + (size_t)b1i * DIN * NPTS;
            for (int j = t; j < 64 * CIN0; j += 512) {
                int c = j >> 6, k = j & 63;
                int gi = k >> 5;
                int nk = nbr[k];
                const float* px = gi ? px1 : px0;
                const float* pp = gi ? pp1 : pp0;
                float v = (c < 3) ? (px[c * NPTS + nk] - qp[gi * 3 + c])
                                  : pp[(c - 3) * NPTS + nk];
                X0t[c * 64 + k] = v;
            }
        }
        __syncthreads();

        // ---- Layer 0: 67 -> 64, tile 2k x 4o ----
        {
            unsigned long long a00 = 0, a01 = 0, a10 = 0, a11 = 0;
#pragma unroll 4
            for (int c = 0; c < CIN0; c++) {
                float2 xv = *(const float2*)&X0t[c * 64 + k0a];
                ulonglong2 w = *(const ulonglong2*)&W0t[c * 64 + o0];
                unsigned long long x0, x1;
                PACK2(x0, xv.x); PACK2(x1, xv.y);
                FMA2(a00, x0, w.x); FMA2(a01, x0, w.y);
                FMA2(a10, x1, w.x); FMA2(a11, x1, w.y);
            }
            float v[2][4];
            UNPACK2(v[0][0], v[0][1], a00); UNPACK2(v[0][2], v[0][3], a01);
            UNPACK2(v[1][0], v[1][1], a10); UNPACK2(v[1][2], v[1][3], a11);
#pragma unroll
            for (int j = 0; j < 4; j++) {
                int c = o0 + j;
                float2 hv = make_float2(silu_f(v[0][j] + bias0[j]),
                                        silu_f(v[1][j] + bias0[j]));
                *(float2*)&H1t[c * 64 + SWZ(c, k0a)] = hv;
            }
        }
        __syncthreads();

        // ---- Layer 1: 64 -> 128, tile 4k x 4o; cb-blocked const swizzle ----
        {
            unsigned long long a[2][4];
#pragma unroll
            for (int kp = 0; kp < 2; kp++)
#pragma unroll
                for (int j = 0; j < 4; j++) a[kp][j] = 0;
            const float* h1b = H1t + k1;
            const float* w1b = W1t + o1;
            for (int cb = 0; cb < H1DIM; cb += 32) {
#pragma unroll
                for (int u = 0; u < 32; u++) {
                    const int c = cb + u;
                    ulonglong2 xv = *(const ulonglong2*)&h1b[c * 64 + (SWZ(c, k1) - k1)];
                    float4 wv = *(const float4*)&w1b[c * 128];
                    unsigned long long w0d, w1d, w2d, w3d;
                    PACK2(w0d, wv.x); PACK2(w1d, wv.y); PACK2(w2d, wv.z); PACK2(w3d, wv.w);
                    FMA2(a[0][0], xv.x, w0d); FMA2(a[0][1], xv.x, w1d);
                    FMA2(a[0][2], xv.x, w2d); FMA2(a[0][3], xv.x, w3d);
                    FMA2(a[1][0], xv.y, w0d); FMA2(a[1][1], xv.y, w1d);
                    FMA2(a[1][2], xv.y, w2d); FMA2(a[1][3], xv.y, w3d);
                }
            }
            float v[4][4];
#pragma unroll
            for (int kp = 0; kp < 2; kp++)
#pragma unroll
                for (int j = 0; j < 4; j++)
                    UNPACK2(v[2 * kp][j], v[2 * kp + 1][j], a[kp][j]);
#pragma unroll
            for (int j = 0; j < 4; j++) {
                int c = o1 + j;
                float4 hv = make_float4(silu_f(v[0][j] + bias1[j]),
                                        silu_f(v[1][j] + bias1[j]),
                                        silu_f(v[2][j] + bias1[j]),
                                        silu_f(v[3][j] + bias1[j]));
                *(float4*)&H2t[c * 64 + SWZ(c, k1)] = hv;
            }
        }
        __syncthreads();

        // ---- Layer 2: 128 -> 256, tile 8k x 4o; cb-blocked const swizzle ----
        {
            unsigned long long a[4][4];
#pragma unroll
            for (int kp = 0; kp < 4; kp++)
#pragma unroll
                for (int j = 0; j < 4; j++) a[kp][j] = 0;
            const float* h2a = H2t + k2;
            const float* h2b = H2t + k2 + 4;
            const float* w2b = W2t + o2;
            for (int cb = 0; cb < H2DIM; cb += 32) {
#pragma unroll
                for (int u = 0; u < 32; u++) {
                    const int c = cb + u;
                    ulonglong2 xa = *(const ulonglong2*)&h2a[c * 64 + (SWZ(c, k2) - k2)];
                    ulonglong2 xb = *(const ulonglong2*)&h2b[c * 64 + (SWZ(c, k2 + 4) - (k2 + 4))];
                    float4 wv = *(const float4*)&w2b[c * 256];
                    unsigned long long w0d, w1d, w2d, w3d;
                    PACK2(w0d, wv.x); PACK2(w1d, wv.y); PACK2(w2d, wv.z); PACK2(w3d, wv.w);
                    FMA2(a[0][0], xa.x, w0d); FMA2(a[0][1], xa.x, w1d);
                    FMA2(a[0][2], xa.x, w2d); FMA2(a[0][3], xa.x, w3d);
                    FMA2(a[1][0], xa.y, w0d); FMA2(a[1][1], xa.y, w1d);
                    FMA2(a[1][2], xa.y, w2d); FMA2(a[1][3], xa.y, w3d);
                    FMA2(a[2][0], xb.x, w0d); FMA2(a[2][1], xb.x, w1d);
                    FMA2(a[2][2], xb.x, w2d); FMA2(a[2][3], xb.x, w3d);
                    FMA2(a[3][0], xb.y, w0d); FMA2(a[3][1], xb.y, w1d);
                    FMA2(a[3][2], xb.y, w2d); FMA2(a[3][3], xb.y, w3d);
                }
            }
            float u2[8][4];
#pragma unroll
            for (int kp = 0; kp < 4; kp++)
#pragma unroll
                for (int j = 0; j < 4; j++)
                    UNPACK2(u2[2 * kp][j], u2[2 * kp + 1][j], a[kp][j]);
            float part[4];
#pragma unroll
            for (int j = 0; j < 4; j++) {
                float bb = bias2[j];
                float sum = silu_f(u2[0][j] + bb);
#pragma unroll
                for (int kk = 1; kk < 8; kk++) sum += silu_f(u2[kk][j] + bb);
                part[j] = sum;
            }
            // Red aliases H1t: last H1t reads completed at the post-L1 sync
            *(float4*)&Red[kt2 * 256 + o2] = make_float4(part[0], part[1], part[2], part[3]);
        }
        __syncthreads();

        // mean/out + stage NEXT group's nbr/qp in the same phase
        {
            int gi = t >> 8;
            int o  = t & 255;
            float sum = 0.0f;
#pragma unroll
            for (int r = 0; r < 4; r++) sum += Red[(gi * 4 + r) * 256 + o];
            int g = g0 + gi;
            int b = g >> 10;
            int s = g & 1023;
            out[(size_t)b * (H3DIM * NPOINT) + (size_t)o * NPOINT + s] = sum * (1.0f / 32.0f);
        }
        {
            int npg = pg + gridDim.x;
            if (npg < NG) {
                const int ng0 = npg * 2;
                if (t < 64) nbr[t] = g_nb[(ng0 + (t >> 5)) * NSAMP + (t & 31)];
                if (t >= 64 && t < 66) {
                    int gi = t - 64;
                    int g = ng0 + gi;
                    int b = g >> 10;
                    const float* px = xyz + (size_t)b * 3 * NPTS;
                    int qi = g_fps[g];
                    qp[gi * 3 + 0] = px[qi];
                    qp[gi * 3 + 1] = px[NPTS + qi];
                    qp[gi * 3 + 2] = px[2 * NPTS + qi];
                }
            }
        }
        __syncthreads();
    }
}

// ---------------------------------------------------------------------------
extern "C" void kernel_launch(void* const* d_in, const int* in_sizes, int n_in,
                              void* d_out, int out_size) {
    const float* xyz = (const float*)d_in[0];
    const float* pts = (const float*)d_in[1];
    const float* w0  = (const float*)d_in[2];
    const float* b0  = (const float*)d_in[3];
    const float* w1  = (const float*)d_in[4];
    const float* b1  = (const float*)d_in[5];
    const float* w2  = (const float*)d_in[6];
    const float* b2  = (const float*)d_in[7];
    float* out = (float*)d_out;

    const int fps_smem = 3 * NPTS * (int)sizeof(float);           // 196608 B
    const int mlp_smem = MLP_SMEM_FLOATS * (int)sizeof(float);    // 230432 B
    cudaFuncSetAttribute(fps_kernel, cudaFuncAttributeMaxDynamicSharedMemorySize, fps_smem);
    cudaFuncSetAttribute(mlp_kernel, cudaFuncAttributeMaxDynamicSharedMemorySize, mlp_smem);

    fps_kernel<<<B_BAT * 8, 256, fps_smem>>>(xyz);
    bq_prep_kernel<<<BQ_BLOCKS + PREP_BLOCKS, 256>>>(xyz, w0, w1, w2);
    mlp_kernel<<<148, 512, mlp_smem>>>(xyz, pts, b0, b1, b2, out);
}